// round 8
// baseline (speedup 1.0000x reference)
#include <cuda_runtime.h>
#include <cuda_bf16.h>

#define NPTS   65536
#define MG     1024
#define KTOP   10
#define NTHR   64
#define NBLK   (NPTS / NTHR)

// -0.5 * log2(e): fold exp(-0.5*quad) -> exp2(g) with g = L*quad
#define LFAC   (-0.72134752044448170367996234050095f)

__global__ __launch_bounds__(NTHR)
void RendererTopK_32134945309178_kernel(const float* __restrict__ x,
                                        const float* __restrict__ mus,
                                        const float* __restrict__ covs,
                                        const float* __restrict__ cols,
                                        float* __restrict__ out)
{
    // Precomputed per-gaussian params in SMEM (broadcast reads in mainloop)
    __shared__ float4 sp[MG];        // {mx, my, ka, kb}
    __shared__ float  skc[MG];       // kc
    __shared__ float  scol[MG * 3];  // colors

    // ---- per-block precompute: invert 2x2 SPD cov, fold -0.5*log2e ----
    for (int m = threadIdx.x; m < MG; m += NTHR) {
        float mx  = mus[2*m + 0];
        float my  = mus[2*m + 1];
        float c00 = covs[4*m + 0];
        float c01 = covs[4*m + 1];   // == covs[4*m+2] (symmetric)
        float c11 = covs[4*m + 3];
        float det = fmaf(c00, c11, -c01 * c01);
        float s   = LFAC / det;
        // quad = (c11*dx^2 - 2*c01*dx*dy + c00*dy^2)/det ; g = LFAC*quad
        sp[m]  = make_float4(mx, my, c11 * s, -2.0f * c01 * s);
        skc[m] = c00 * s;
        scol[3*m + 0] = cols[3*m + 0];
        scol[3*m + 1] = cols[3*m + 1];
        scol[3*m + 2] = cols[3*m + 2];
    }
    __syncthreads();

    const int n = blockIdx.x * NTHR + threadIdx.x;
    const float px = x[2*n + 0];
    const float py = x[2*n + 1];

    // top-10 largest g (== top-10 largest gauss weight), sorted descending
    float qv[KTOP];
    int   qi[KTOP];
#pragma unroll
    for (int i = 0; i < KTOP; i++) { qv[i] = -1e30f; qi[i] = 0; }
    float worst = -1e30f;

#pragma unroll 4
    for (int m = 0; m < MG; m++) {
        const float4 p  = sp[m];
        const float  kc = skc[m];
        const float dx = px - p.x;
        const float dy = py - p.y;
        const float g  = fmaf(p.z, dx*dx, fmaf(p.w, dx*dy, kc * (dy*dy)));
        if (g > worst) {
            float cv = g; int ci = m;
#pragma unroll
            for (int i = 0; i < KTOP; i++) {
                if (cv > qv[i]) {
                    float tv = qv[i]; int ti = qi[i];
                    qv[i] = cv; qi[i] = ci;
                    cv = tv;    ci = ti;
                }
            }
            worst = qv[KTOP - 1];
        }
    }

    // exp2 only for the 10 winners; weighted color sum + normalize
    float sum = 0.0f, cr = 0.0f, cg = 0.0f, cb = 0.0f;
#pragma unroll
    for (int i = 0; i < KTOP; i++) {
        float v;
        asm("ex2.approx.ftz.f32 %0, %1;" : "=f"(v) : "f"(qv[i]));
        const int id = qi[i];
        sum += v;
        cr = fmaf(v, scol[3*id + 0], cr);
        cg = fmaf(v, scol[3*id + 1], cg);
        cb = fmaf(v, scol[3*id + 2], cb);
    }
    const float inv = 1.0f / (sum + 1e-6f);
    out[3*n + 0] = cr * inv;
    out[3*n + 1] = cg * inv;
    out[3*n + 2] = cb * inv;
}

extern "C" void kernel_launch(void* const* d_in, const int* in_sizes, int n_in,
                              void* d_out, int out_size)
{
    // Resolve inputs by element count (robust to metadata ordering):
    //   x: 65536*2 = 131072, mus: 1024*2 = 2048, covs: 1024*4 = 4096, cols: 1024*3 = 3072
    const float* x    = nullptr;
    const float* mus  = nullptr;
    const float* covs = nullptr;
    const float* cols = nullptr;
    for (int i = 0; i < n_in; i++) {
        switch (in_sizes[i]) {
            case 131072: x    = (const float*)d_in[i]; break;
            case 2048:   mus  = (const float*)d_in[i]; break;
            case 4096:   covs = (const float*)d_in[i]; break;
            case 3072:   cols = (const float*)d_in[i]; break;
            default: break;
        }
    }
    RendererTopK_32134945309178_kernel<<<NBLK, NTHR>>>(x, mus, covs, cols,
                                                       (float*)d_out);
}

// round 13
// speedup vs baseline: 1.4979x; 1.4979x over previous
#include <cuda_runtime.h>
#include <cuda_bf16.h>

#define NPTS   65536
#define MG     1024
#define KTOP   10
#define NTHR   64
#define NBLK   (NPTS / NTHR)

// -0.5 * log2(e): fold exp(-0.5*quad) -> exp2(g) with g = LFAC*quad
#define LFAC   (-0.72134752044448170367996234050095f)

__global__ __launch_bounds__(NTHR)
void RendererTopK_32134945309178_kernel(const float* __restrict__ x,
                                        const float* __restrict__ mus,
                                        const float* __restrict__ covs,
                                        const float* __restrict__ cols,
                                        float* __restrict__ out)
{
    // Per-gaussian params in SMEM (broadcast reads, conflict-free).
    // Colors intentionally NOT in SMEM: 20.5KB/block -> 11 blocks/SM resident.
    __shared__ float4 sp[MG];        // {mx, my, ka, kb}
    __shared__ float  skc[MG];       // kc

    // ---- precompute: invert 2x2 SPD cov, fold -0.5*log2e into coeffs ----
    for (int m = threadIdx.x; m < MG; m += NTHR) {
        float mx  = mus[2*m + 0];
        float my  = mus[2*m + 1];
        float c00 = covs[4*m + 0];
        float c01 = covs[4*m + 1];   // symmetric
        float c11 = covs[4*m + 3];
        float det = fmaf(c00, c11, -c01 * c01);
        float s   = LFAC / det;
        sp[m]  = make_float4(mx, my, c11 * s, -2.0f * c01 * s);
        skc[m] = c00 * s;
    }
    __syncthreads();

    const int n = blockIdx.x * NTHR + threadIdx.x;
    const float px = x[2*n + 0];
    const float py = x[2*n + 1];

    // ---- Pass A: branchless top-10 VALUES (sorted descending) ----
    // Insert v: q[i] <- min(max(v, q[i]), q[i-1]) for i = 9..1 (old values),
    //           q[0] <- max(v, q[0]).  2 FMNMX/slot, zero divergence.
    float q[KTOP];
#pragma unroll
    for (int i = 0; i < KTOP; i++) q[i] = -1e30f;

#pragma unroll 8
    for (int m = 0; m < MG; m++) {
        const float4 p  = sp[m];
        const float  kc = skc[m];
        const float dx = px - p.x;
        const float dy = py - p.y;
        const float t1 = fmaf(p.w, dy, p.z * dx);   // ka*dx + kb*dy
        const float t2 = (kc * dy) * dy;            // kc*dy^2
        const float v  = fmaf(dx, t1, t2);          // g (log2-domain weight)
#pragma unroll
        for (int i = KTOP - 1; i >= 1; i--)
            q[i] = fminf(fmaxf(v, q[i]), q[i - 1]); // reads OLD q[i-1]
        q[0] = fmaxf(v, q[0]);
    }

    const float thr = q[KTOP - 1];   // 10th largest g

    // ---- Pass B: recompute g (identical expression -> identical bits),
    //      accumulate exp2(g)*color for the top-10 hits only ----
    float sum = 0.0f, cr = 0.0f, cg = 0.0f, cb = 0.0f;
#pragma unroll 4
    for (int m = 0; m < MG; m++) {
        const float4 p  = sp[m];
        const float  kc = skc[m];
        const float dx = px - p.x;
        const float dy = py - p.y;
        const float t1 = fmaf(p.w, dy, p.z * dx);
        const float t2 = (kc * dy) * dy;
        const float g  = fmaf(dx, t1, t2);
        if (g >= thr) {
            float w;
            asm("ex2.approx.ftz.f32 %0, %1;" : "=f"(w) : "f"(g));
            sum += w;
            cr = fmaf(w, __ldg(&cols[3*m + 0]), cr);
            cg = fmaf(w, __ldg(&cols[3*m + 1]), cg);
            cb = fmaf(w, __ldg(&cols[3*m + 2]), cb);
        }
    }

    const float inv = 1.0f / (sum + 1e-6f);
    out[3*n + 0] = cr * inv;
    out[3*n + 1] = cg * inv;
    out[3*n + 2] = cb * inv;
}

extern "C" void kernel_launch(void* const* d_in, const int* in_sizes, int n_in,
                              void* d_out, int out_size)
{
    // Resolve inputs by element count (robust to metadata ordering):
    //   x: 65536*2 = 131072, mus: 1024*2 = 2048, covs: 1024*4 = 4096, cols: 1024*3 = 3072
    const float* x    = nullptr;
    const float* mus  = nullptr;
    const float* covs = nullptr;
    const float* cols = nullptr;
    for (int i = 0; i < n_in; i++) {
        switch (in_sizes[i]) {
            case 131072: x    = (const float*)d_in[i]; break;
            case 2048:   mus  = (const float*)d_in[i]; break;
            case 4096:   covs = (const float*)d_in[i]; break;
            case 3072:   cols = (const float*)d_in[i]; break;
            default: break;
        }
    }
    RendererTopK_32134945309178_kernel<<<NBLK, NTHR>>>(x, mus, covs, cols,
                                                       (float*)d_out);
}

// round 15
// speedup vs baseline: 1.7759x; 1.1856x over previous
#include <cuda_runtime.h>
#include <cuda_bf16.h>

#define NPTS   65536
#define MG     1024
#define KTOP   10
#define NTHR   128                  // 4 warps/block; 2 lanes per point
#define PPB    (NTHR / 2)           // 64 points per block
#define NBLK   (NPTS / PPB)         // 1024 blocks
#define MSEG   (MG / 2)             // 512 gaussians per lane

// -0.5 * log2(e): fold exp(-0.5*quad) -> exp2(g) with g = LFAC*quad
#define LFAC   (-0.72134752044448170367996234050095f)

__global__ __launch_bounds__(NTHR)
void RendererTopK_32134945309178_kernel(const float* __restrict__ x,
                                        const float* __restrict__ mus,
                                        const float* __restrict__ covs,
                                        const float* __restrict__ cols,
                                        float* __restrict__ out)
{
    // Per-gaussian params in SMEM (broadcast reads, conflict-free).
    __shared__ float4 sp[MG];        // {mx, my, ka, kb}
    __shared__ float  skc[MG];       // kc

    // ---- precompute: invert 2x2 SPD cov, fold -0.5*log2e into coeffs ----
    for (int m = threadIdx.x; m < MG; m += NTHR) {
        float mx  = mus[2*m + 0];
        float my  = mus[2*m + 1];
        float c00 = covs[4*m + 0];
        float c01 = covs[4*m + 1];   // symmetric
        float c11 = covs[4*m + 3];
        float det = fmaf(c00, c11, -c01 * c01);
        float s   = LFAC / det;
        sp[m]  = make_float4(mx, my, c11 * s, -2.0f * c01 * s);
        skc[m] = c00 * s;
    }
    __syncthreads();

    // Two lanes per point: lane pair (2k, 2k+1); seg selects gaussian half.
    const int n   = blockIdx.x * PPB + (threadIdx.x >> 1);
    const int seg = threadIdx.x & 1;
    const int m0  = seg * MSEG;
    const float px = x[2*n + 0];
    const float py = x[2*n + 1];

    // ---- Pass A: branchless per-lane top-10 over this lane's 512 gaussians ----
    float q[KTOP];
#pragma unroll
    for (int i = 0; i < KTOP; i++) q[i] = -1e30f;

#pragma unroll 8
    for (int mm = 0; mm < MSEG; mm++) {
        const int m = m0 + mm;
        const float4 p  = sp[m];
        const float  kc = skc[m];
        const float dx = px - p.x;
        const float dy = py - p.y;
        const float t1 = fmaf(p.w, dy, p.z * dx);   // ka*dx + kb*dy
        const float t2 = (kc * dy) * dy;            // kc*dy^2
        const float v  = fmaf(dx, t1, t2);          // g (log2-domain weight)
#pragma unroll
        for (int i = KTOP - 1; i >= 1; i--)
            q[i] = fminf(fmaxf(v, q[i]), q[i - 1]); // reads OLD q[i-1]
        q[0] = fmaxf(v, q[0]);
    }

    // ---- merge partner's sorted top-10: 10th largest of the union is
    //      min_i max(a[i], b[9-i])  (bitonic top-k merge identity).
    //      Symmetric in a<->b, so both lanes get bitwise-identical thr.
    float b[KTOP];
#pragma unroll
    for (int i = 0; i < KTOP; i++)
        b[i] = __shfl_xor_sync(0xffffffffu, q[i], 1);

    float thr = fmaxf(q[0], b[KTOP - 1]);
#pragma unroll
    for (int i = 1; i < KTOP; i++)
        thr = fminf(thr, fmaxf(q[i], b[KTOP - 1 - i]));

    // ---- Pass B: recompute g over this lane's segment (identical expression
    //      -> identical bits), accumulate exp2(g)*color for hits ----
    float sum = 0.0f, cr = 0.0f, cg = 0.0f, cb = 0.0f;
#pragma unroll 4
    for (int mm = 0; mm < MSEG; mm++) {
        const int m = m0 + mm;
        const float4 p  = sp[m];
        const float  kc = skc[m];
        const float dx = px - p.x;
        const float dy = py - p.y;
        const float t1 = fmaf(p.w, dy, p.z * dx);
        const float t2 = (kc * dy) * dy;
        const float g  = fmaf(dx, t1, t2);
        if (g >= thr) {
            float w;
            asm("ex2.approx.ftz.f32 %0, %1;" : "=f"(w) : "f"(g));
            sum += w;
            cr = fmaf(w, __ldg(&cols[3*m + 0]), cr);
            cg = fmaf(w, __ldg(&cols[3*m + 1]), cg);
            cb = fmaf(w, __ldg(&cols[3*m + 2]), cb);
        }
    }

    // pair-reduce the 4 accumulators; even lane writes
    sum += __shfl_xor_sync(0xffffffffu, sum, 1);
    cr  += __shfl_xor_sync(0xffffffffu, cr, 1);
    cg  += __shfl_xor_sync(0xffffffffu, cg, 1);
    cb  += __shfl_xor_sync(0xffffffffu, cb, 1);

    if (seg == 0) {
        const float inv = 1.0f / (sum + 1e-6f);
        out[3*n + 0] = cr * inv;
        out[3*n + 1] = cg * inv;
        out[3*n + 2] = cb * inv;
    }
}

extern "C" void kernel_launch(void* const* d_in, const int* in_sizes, int n_in,
                              void* d_out, int out_size)
{
    // Resolve inputs by element count (robust to metadata ordering):
    //   x: 65536*2 = 131072, mus: 1024*2 = 2048, covs: 1024*4 = 4096, cols: 1024*3 = 3072
    const float* x    = nullptr;
    const float* mus  = nullptr;
    const float* covs = nullptr;
    const float* cols = nullptr;
    for (int i = 0; i < n_in; i++) {
        switch (in_sizes[i]) {
            case 131072: x    = (const float*)d_in[i]; break;
            case 2048:   mus  = (const float*)d_in[i]; break;
            case 4096:   covs = (const float*)d_in[i]; break;
            case 3072:   cols = (const float*)d_in[i]; break;
            default: break;
        }
    }
    RendererTopK_32134945309178_kernel<<<NBLK, NTHR>>>(x, mus, covs, cols,
                                                       (float*)d_out);
}

// round 16
// speedup vs baseline: 1.8384x; 1.0352x over previous
#include <cuda_runtime.h>
#include <cuda_bf16.h>

#define NPTS   65536
#define MG     1024
#define KTOP   10
#define NTHR   128                  // 4 warps/block; 4 lanes per point
#define SEGS   4
#define PPB    (NTHR / SEGS)        // 32 points per block
#define NBLK   (NPTS / PPB)         // 2048 blocks
#define MSEG   (MG / SEGS)          // 256 gaussians per lane

// -0.5 * log2(e): fold exp(-0.5*quad) -> exp2(g) with g = LFAC*quad
#define LFAC   (-0.72134752044448170367996234050095f)

__global__ __launch_bounds__(NTHR)
void RendererTopK_32134945309178_kernel(const float* __restrict__ x,
                                        const float* __restrict__ mus,
                                        const float* __restrict__ covs,
                                        const float* __restrict__ cols,
                                        float* __restrict__ out)
{
    // Per-gaussian params in SMEM (broadcast reads, conflict-free).
    __shared__ float4 sp[MG];        // {mx, my, ka, kb}
    __shared__ float  skc[MG];       // kc

    // ---- precompute: invert 2x2 SPD cov, fold -0.5*log2e into coeffs ----
    for (int m = threadIdx.x; m < MG; m += NTHR) {
        float mx  = mus[2*m + 0];
        float my  = mus[2*m + 1];
        float c00 = covs[4*m + 0];
        float c01 = covs[4*m + 1];   // symmetric
        float c11 = covs[4*m + 3];
        float det = fmaf(c00, c11, -c01 * c01);
        float s   = LFAC / det;
        sp[m]  = make_float4(mx, my, c11 * s, -2.0f * c01 * s);
        skc[m] = c00 * s;
    }
    __syncthreads();

    // 4 lanes per point; seg = lane&3. INTERLEAVED gaussian assignment
    // m = 4*mm + seg: the warp's 4 distinct LDS addresses are contiguous
    // (16B apart) -> conflict-free. Blocked assignment (seg*256+mm) would
    // put all 4 addresses 4096B apart = same bank = 4-way conflict.
    const int n   = blockIdx.x * PPB + (threadIdx.x >> 2);
    const int seg = threadIdx.x & 3;
    const float px = x[2*n + 0];
    const float py = x[2*n + 1];

    // ---- Pass A: branchless per-lane top-10 over 256 gaussians ----
    float q[KTOP];
#pragma unroll
    for (int i = 0; i < KTOP; i++) q[i] = -1e30f;

#pragma unroll 8
    for (int mm = 0; mm < MSEG; mm++) {
        const int m = (mm << 2) | seg;
        const float4 p  = sp[m];
        const float  kc = skc[m];
        const float dx = px - p.x;
        const float dy = py - p.y;
        const float t1 = fmaf(p.w, dy, p.z * dx);   // ka*dx + kb*dy
        const float t2 = (kc * dy) * dy;            // kc*dy^2
        const float v  = fmaf(dx, t1, t2);          // g (log2-domain weight)
#pragma unroll
        for (int i = KTOP - 1; i >= 1; i--)
            q[i] = fminf(fmaxf(v, q[i]), q[i - 1]); // reads OLD q[i-1]
        q[0] = fmaxf(v, q[0]);
    }

    // ---- merge round 1 (xor 1): FULL sorted top-10 of pairwise union.
    //      merged[i] = max(q[i], b[i], max_{j<i} min(q[j], b[i-1-j]))
    //      Exact min/max, symmetric in q<->b -> both lanes bit-identical.
    float b[KTOP];
#pragma unroll
    for (int i = 0; i < KTOP; i++)
        b[i] = __shfl_xor_sync(0xffffffffu, q[i], 1);

    float r[KTOP];
#pragma unroll
    for (int i = 0; i < KTOP; i++) {
        float t = fmaxf(q[i], b[i]);
#pragma unroll
        for (int j = 0; j < i; j++)
            t = fmaxf(t, fminf(q[j], b[i - 1 - j]));
        r[i] = t;
    }

    // ---- merge round 2 (xor 2): only need the 10th largest of the union:
    //      thr = min_i max(r[i], d[9-i])   (bitonic top-k identity)
    float d9[KTOP];
#pragma unroll
    for (int i = 0; i < KTOP; i++)
        d9[i] = __shfl_xor_sync(0xffffffffu, r[i], 2);

    float thr = fmaxf(r[0], d9[KTOP - 1]);
#pragma unroll
    for (int i = 1; i < KTOP; i++)
        thr = fminf(thr, fmaxf(r[i], d9[KTOP - 1 - i]));

    // ---- Pass B: recompute g (identical expression -> identical bits),
    //      accumulate exp2(g)*color for the top-10 hits only ----
    float sum = 0.0f, cr = 0.0f, cg = 0.0f, cb = 0.0f;
#pragma unroll 4
    for (int mm = 0; mm < MSEG; mm++) {
        const int m = (mm << 2) | seg;
        const float4 p  = sp[m];
        const float  kc = skc[m];
        const float dx = px - p.x;
        const float dy = py - p.y;
        const float t1 = fmaf(p.w, dy, p.z * dx);
        const float t2 = (kc * dy) * dy;
        const float g  = fmaf(dx, t1, t2);
        if (g >= thr) {
            float w;
            asm("ex2.approx.ftz.f32 %0, %1;" : "=f"(w) : "f"(g));
            sum += w;
            cr = fmaf(w, __ldg(&cols[3*m + 0]), cr);
            cg = fmaf(w, __ldg(&cols[3*m + 1]), cg);
            cb = fmaf(w, __ldg(&cols[3*m + 2]), cb);
        }
    }

    // reduce the 4 accumulators across the lane quad; seg 0 writes
    sum += __shfl_xor_sync(0xffffffffu, sum, 1);
    cr  += __shfl_xor_sync(0xffffffffu, cr, 1);
    cg  += __shfl_xor_sync(0xffffffffu, cg, 1);
    cb  += __shfl_xor_sync(0xffffffffu, cb, 1);
    sum += __shfl_xor_sync(0xffffffffu, sum, 2);
    cr  += __shfl_xor_sync(0xffffffffu, cr, 2);
    cg  += __shfl_xor_sync(0xffffffffu, cg, 2);
    cb  += __shfl_xor_sync(0xffffffffu, cb, 2);

    if (seg == 0) {
        const float inv = 1.0f / (sum + 1e-6f);
        out[3*n + 0] = cr * inv;
        out[3*n + 1] = cg * inv;
        out[3*n + 2] = cb * inv;
    }
}

extern "C" void kernel_launch(void* const* d_in, const int* in_sizes, int n_in,
                              void* d_out, int out_size)
{
    // Resolve inputs by element count (robust to metadata ordering):
    //   x: 65536*2 = 131072, mus: 1024*2 = 2048, covs: 1024*4 = 4096, cols: 1024*3 = 3072
    const float* x    = nullptr;
    const float* mus  = nullptr;
    const float* covs = nullptr;
    const float* cols = nullptr;
    for (int i = 0; i < n_in; i++) {
        switch (in_sizes[i]) {
            case 131072: x    = (const float*)d_in[i]; break;
            case 2048:   mus  = (const float*)d_in[i]; break;
            case 4096:   covs = (const float*)d_in[i]; break;
            case 3072:   cols = (const float*)d_in[i]; break;
            default: break;
        }
    }
    RendererTopK_32134945309178_kernel<<<NBLK, NTHR>>>(x, mus, covs, cols,
                                                       (float*)d_out);
}